// round 2
// baseline (speedup 1.0000x reference)
#include <cuda_runtime.h>

#define H      128
#define W      128
#define NLAM   128
#define BATCH  16
#define NK     4
#define HP     192
#define WP     192
#define RPW    24          // output rows per warp

// scratch accumulator: (B*NK, HP, WP) = 9.4 MB
__device__ float g_acc[BATCH * NK * HP * WP];

// ---------------------------------------------------------------------------
// Kernel 1: per-(b,k) accumulate over wavelengths of uniformly-shifted slices.
// Block: (32, 8). lane = output column (coalesced loads). Warp w owns rows
// [24w, 24w+24). Block covers 32 cols x 192 rows. Grid: (6, 1, B*NK).
//
// out(y,x) += fy*fx*in[y-33-ny, x-33-nx] + fy*gx*in[y-33-ny, x-32-nx]
//           + gy*fx*in[y-32-ny, x-33-nx] + gy*gx*in[y-32-ny, x-32-nx]
// i.e. with c0 = x-33-nx, ry(r) = y0+r-33-ny:
//   h[r] = fx*in[ry(r)][c0] + gx*in[ry(r)][c0+1]
//   acc[r] += fy*h[r];  acc[r-1] += gy*h[r]
// ---------------------------------------------------------------------------
__global__ __launch_bounds__(256) void accum_kernel(
    const float* __restrict__ cube,   // (B, NLAM, H, W)
    const float* __restrict__ dx,     // (NK, NLAM)
    const float* __restrict__ dy)     // (NK, NLAM)
{
    __shared__ int   s_nx[NLAM], s_ny[NLAM];
    __shared__ float s_fx[NLAM], s_gx[NLAM], s_fy[NLAM], s_gy[NLAM];

    const int bz = blockIdx.z;
    const int b  = bz >> 2;
    const int k  = bz & 3;

    const int tid = threadIdx.y * 32 + threadIdx.x;
    if (tid < NLAM) {
        float dxv = dx[k * NLAM + tid];
        float dyv = dy[k * NLAM + tid];
        float nxf = floorf(dxv), nyf = floorf(dyv);
        s_nx[tid] = (int)nxf;
        s_ny[tid] = (int)nyf;
        float fx = dxv - nxf, fy = dyv - nyf;
        s_fx[tid] = fx;  s_gx[tid] = 1.0f - fx;
        s_fy[tid] = fy;  s_gy[tid] = 1.0f - fy;
    }
    __syncthreads();

    const int w    = threadIdx.y;              // warp id 0..7
    const int lane = threadIdx.x;
    const int x    = blockIdx.x * 32 + lane;   // output col
    const int y0   = w * RPW;                  // output row base

    float acc[RPW];
    #pragma unroll
    for (int i = 0; i < RPW; ++i) acc[i] = 0.0f;

    const float* cb = cube + (size_t)b * NLAM * H * W;

    for (int l = 0; l < NLAM; ++l) {
        const int nx = s_nx[l];
        const int ny = s_ny[l];
        const int c0  = x - 33 - nx;                 // per-lane input col (fx tap)
        const int cw  = blockIdx.x * 32 - 33 - nx;   // block col window [cw, cw+32]
        const int ry0 = y0 - 33 - ny;                // warp row window [ry0, ry0+RPW]

        // warp-uniform skips: fully out-of-bounds contributes exactly zero
        if (cw > W - 1 || cw + 32 < 0) continue;
        if (ry0 > H - 1 || ry0 + RPW < 0) continue;

        const float fx = s_fx[l], gx = s_gx[l];
        const float fy = s_fy[l], gy = s_gy[l];
        const float* sl = cb + l * H * W;
        const float* p0 = sl + ry0 * W + c0;         // deref only when predicated valid

        const bool cv0 = ((unsigned)c0       < (unsigned)W);
        const bool cv1 = ((unsigned)(c0 + 1) < (unsigned)W);

        if (fy == 0.0f) {
            // pure-x shift (k=0 data): gy == 1, only rows r=1..RPW matter
            #pragma unroll
            for (int r = 1; r <= RPW; ++r) {
                bool rv = ((unsigned)(ry0 + r) < (unsigned)H);
                float v0 = (rv && cv0) ? __ldg(p0 + r * W)     : 0.0f;
                float v1 = (rv && cv1) ? __ldg(p0 + r * W + 1) : 0.0f;
                acc[r - 1] += fx * v0 + gx * v1;
            }
        } else if (fx == 0.0f) {
            // pure-y shift: gx == 1, single column tap at c0+1
            #pragma unroll
            for (int r = 0; r <= RPW; ++r) {
                bool rv = ((unsigned)(ry0 + r) < (unsigned)H);
                float h = (rv && cv1) ? __ldg(p0 + r * W + 1) : 0.0f;
                if (r > 0)   acc[r - 1] += gy * h;
                if (r < RPW) acc[r]     += fy * h;
            }
        } else {
            #pragma unroll
            for (int r = 0; r <= RPW; ++r) {
                bool rv = ((unsigned)(ry0 + r) < (unsigned)H);
                float v0 = (rv && cv0) ? __ldg(p0 + r * W)     : 0.0f;
                float v1 = (rv && cv1) ? __ldg(p0 + r * W + 1) : 0.0f;
                float h = fx * v0 + gx * v1;
                if (r > 0)   acc[r - 1] += gy * h;
                if (r < RPW) acc[r]     += fy * h;
            }
        }
    }

    float* ap = g_acc + ((size_t)bz * HP + y0) * WP + x;
    #pragma unroll
    for (int r = 0; r < RPW; ++r)
        ap[r * WP] = acc[r];
}

// ---------------------------------------------------------------------------
// Kernel 2: 7x7 PSF convolution (same padding, zeros), acc -> out.
// Block: (32, 8), output tile 32x32 (each thread 4 consecutive rows).
// Grid: (6, 6, B*NK).
// ---------------------------------------------------------------------------
__global__ __launch_bounds__(256) void conv_kernel(
    const float* __restrict__ psf,    // (7,7)
    float* __restrict__ out)          // (B, NK, HP, WP)
{
    __shared__ float s[38 * 40];
    __shared__ float sp[49];

    const int bz = blockIdx.z;
    const float* ap = g_acc + (size_t)bz * HP * WP;

    const int tid = threadIdx.y * 32 + threadIdx.x;
    if (tid < 49) sp[tid] = psf[tid];

    const int x0 = blockIdx.x * 32;
    const int y0 = blockIdx.y * 32;

    for (int i = tid; i < 38 * 38; i += 256) {
        int r = i / 38, c = i % 38;
        int gy = y0 + r - 3;
        int gx = x0 + c - 3;
        s[r * 40 + c] = (((unsigned)gy < (unsigned)HP) && ((unsigned)gx < (unsigned)WP))
                            ? ap[gy * WP + gx] : 0.0f;
    }
    __syncthreads();

    float w[49];
    #pragma unroll
    for (int i = 0; i < 49; ++i) w[i] = sp[i];

    const int tx = threadIdx.x;
    const int rbase = threadIdx.y * 4;

    float a0 = 0.f, a1 = 0.f, a2 = 0.f, a3 = 0.f;
    #pragma unroll
    for (int rr = 0; rr < 10; ++rr) {
        #pragma unroll
        for (int v = 0; v < 7; ++v) {
            float xv = s[(rbase + rr) * 40 + tx + v];
            if (rr <= 6)            a0 += w[rr * 7 + v] * xv;
            if (rr >= 1 && rr <= 7) a1 += w[(rr - 1) * 7 + v] * xv;
            if (rr >= 2 && rr <= 8) a2 += w[(rr - 2) * 7 + v] * xv;
            if (rr >= 3)            a3 += w[(rr - 3) * 7 + v] * xv;
        }
    }

    float* op = out + ((size_t)bz * HP + y0 + rbase) * WP + x0 + tx;
    op[0 * WP] = a0;
    op[1 * WP] = a1;
    op[2 * WP] = a2;
    op[3 * WP] = a3;
}

extern "C" void kernel_launch(void* const* d_in, const int* in_sizes, int n_in,
                              void* d_out, int out_size)
{
    const float* cube = (const float*)d_in[0];
    const float* psf  = (const float*)d_in[1];
    const float* dx   = (const float*)d_in[2];
    const float* dy   = (const float*)d_in[3];
    float* out = (float*)d_out;

    dim3 gb(6, 1, BATCH * NK), tb(32, 8);
    accum_kernel<<<gb, tb>>>(cube, dx, dy);

    dim3 gc(6, 6, BATCH * NK), tc(32, 8);
    conv_kernel<<<gc, tc>>>(psf, out);
}

// round 3
// speedup vs baseline: 5.3565x; 5.3565x over previous
#include <cuda_runtime.h>

#define H      128
#define W      128
#define NLAM   128
#define BATCH  16
#define NK     4
#define HP     192
#define WP     192

// scratch accumulator: (B*NK, HP, WP) = 9.4 MB
__device__ float g_acc[BATCH * NK * HP * WP];

// ---------------------------------------------------------------------------
// Kernel 1: per-(b,k) accumulate over wavelengths of uniformly-shifted slices.
// Block (32,8): lane = output column (coalesced), warp owns 32 cols x 4 rows.
// Grid: (6, 6, B*NK).
//
// out(y,x) += fy*h(y-33-ny) + gy*h(y-32-ny),  h(r,c) = fx*in[r][c0] + gx*in[r][c0+1]
// with c0 = x-33-nx.
// ---------------------------------------------------------------------------
__global__ __launch_bounds__(256) void accum_kernel(
    const float* __restrict__ cube,   // (B, NLAM, H, W)
    const float* __restrict__ dx,     // (NK, NLAM)
    const float* __restrict__ dy)     // (NK, NLAM)
{
    __shared__ int   s_nx[NLAM], s_ny[NLAM];
    __shared__ float s_fx[NLAM], s_gx[NLAM], s_fy[NLAM], s_gy[NLAM];

    const int bz = blockIdx.z;
    const int b  = bz >> 2;
    const int k  = bz & 3;

    const int tid = threadIdx.y * 32 + threadIdx.x;
    if (tid < NLAM) {
        float dxv = dx[k * NLAM + tid];
        float dyv = dy[k * NLAM + tid];
        float nxf = floorf(dxv), nyf = floorf(dyv);
        s_nx[tid] = (int)nxf;
        s_ny[tid] = (int)nyf;
        float fx = dxv - nxf, fy = dyv - nyf;
        s_fx[tid] = fx;  s_gx[tid] = 1.0f - fx;
        s_fy[tid] = fy;  s_gy[tid] = 1.0f - fy;
    }
    __syncthreads();

    const int lane = threadIdx.x;
    const int xb   = blockIdx.x * 32;                      // block col base
    const int x    = xb + lane;                            // output col
    const int y0   = (blockIdx.y * 8 + threadIdx.y) * 4;   // warp's output row base

    float a0 = 0.f, a1 = 0.f, a2 = 0.f, a3 = 0.f;

    const float* cb = cube + (size_t)b * NLAM * H * W;

    for (int l = 0; l < NLAM; ++l) {
        const int nx = s_nx[l];
        const int ny = s_ny[l];
        const int cw  = xb - 33 - nx;    // warp col window: reads cols [cw, cw+32]
        const int ry0 = y0 - 33 - ny;    // warp row window: reads rows [ry0, ry0+4]

        // warp-uniform skip: fully out-of-bounds contributes exactly zero
        if (cw > W - 1 || cw + 32 < 0) continue;
        if (ry0 > H - 1 || ry0 + 4 < 0) continue;

        const float fx = s_fx[l], gx = s_gx[l];
        const float fy = s_fy[l], gy = s_gy[l];
        const float* sl = cb + l * H * W;
        const int c0 = cw + lane;
        const float* p0 = sl + ry0 * W + c0;

        const bool interior = (cw >= 0) & (cw + 32 <= W - 1) &
                              (ry0 >= 0) & (ry0 + 4 <= H - 1);   // warp-uniform

        if (interior) {
            if (fy == 0.0f) {
                // gy == 1: rows r=1..4 only
                #pragma unroll
                for (int r = 1; r <= 4; ++r) {
                    float v0 = __ldg(p0 + r * W);
                    float v1 = __ldg(p0 + r * W + 1);
                    float h  = fx * v0 + gx * v1;
                    if (r == 1) a0 += h;
                    if (r == 2) a1 += h;
                    if (r == 3) a2 += h;
                    if (r == 4) a3 += h;
                }
            } else {
                #pragma unroll
                for (int r = 0; r <= 4; ++r) {
                    float v0 = __ldg(p0 + r * W);
                    float v1 = __ldg(p0 + r * W + 1);
                    float h  = fx * v0 + gx * v1;
                    if (r >= 1) { if (r == 1) a0 += gy * h;
                                  if (r == 2) a1 += gy * h;
                                  if (r == 3) a2 += gy * h;
                                  if (r == 4) a3 += gy * h; }
                    if (r <= 3) { if (r == 0) a0 += fy * h;
                                  if (r == 1) a1 += fy * h;
                                  if (r == 2) a2 += fy * h;
                                  if (r == 3) a3 += fy * h; }
                }
            }
        } else {
            const bool cv0 = ((unsigned)c0       < (unsigned)W);
            const bool cv1 = ((unsigned)(c0 + 1) < (unsigned)W);
            #pragma unroll
            for (int r = 0; r <= 4; ++r) {
                bool rv = ((unsigned)(ry0 + r) < (unsigned)H);
                float v0 = (rv && cv0) ? __ldg(p0 + r * W)     : 0.0f;
                float v1 = (rv && cv1) ? __ldg(p0 + r * W + 1) : 0.0f;
                float h  = fx * v0 + gx * v1;
                if (r >= 1) { if (r == 1) a0 += gy * h;
                              if (r == 2) a1 += gy * h;
                              if (r == 3) a2 += gy * h;
                              if (r == 4) a3 += gy * h; }
                if (r <= 3) { if (r == 0) a0 += fy * h;
                              if (r == 1) a1 += fy * h;
                              if (r == 2) a2 += fy * h;
                              if (r == 3) a3 += fy * h; }
            }
        }
    }

    float* ap = g_acc + ((size_t)bz * HP + y0) * WP + x;
    ap[0 * WP] = a0;
    ap[1 * WP] = a1;
    ap[2 * WP] = a2;
    ap[3 * WP] = a3;
}

// ---------------------------------------------------------------------------
// Kernel 2: 7x7 PSF convolution (same padding, zeros), acc -> out.
// Block: (32, 8), output tile 32x32 (each thread 4 consecutive rows).
// Grid: (6, 6, B*NK).
// ---------------------------------------------------------------------------
__global__ __launch_bounds__(256) void conv_kernel(
    const float* __restrict__ psf,    // (7,7)
    float* __restrict__ out)          // (B, NK, HP, WP)
{
    __shared__ float s[38 * 40];
    __shared__ float sp[49];

    const int bz = blockIdx.z;
    const float* ap = g_acc + (size_t)bz * HP * WP;

    const int tid = threadIdx.y * 32 + threadIdx.x;
    if (tid < 49) sp[tid] = psf[tid];

    const int x0 = blockIdx.x * 32;
    const int y0 = blockIdx.y * 32;

    for (int i = tid; i < 38 * 38; i += 256) {
        int r = i / 38, c = i % 38;
        int gy = y0 + r - 3;
        int gx = x0 + c - 3;
        s[r * 40 + c] = (((unsigned)gy < (unsigned)HP) && ((unsigned)gx < (unsigned)WP))
                            ? ap[gy * WP + gx] : 0.0f;
    }
    __syncthreads();

    float w[49];
    #pragma unroll
    for (int i = 0; i < 49; ++i) w[i] = sp[i];

    const int tx = threadIdx.x;
    const int rbase = threadIdx.y * 4;

    float a0 = 0.f, a1 = 0.f, a2 = 0.f, a3 = 0.f;
    #pragma unroll
    for (int rr = 0; rr < 10; ++rr) {
        #pragma unroll
        for (int v = 0; v < 7; ++v) {
            float xv = s[(rbase + rr) * 40 + tx + v];
            if (rr <= 6)            a0 += w[rr * 7 + v] * xv;
            if (rr >= 1 && rr <= 7) a1 += w[(rr - 1) * 7 + v] * xv;
            if (rr >= 2 && rr <= 8) a2 += w[(rr - 2) * 7 + v] * xv;
            if (rr >= 3)            a3 += w[(rr - 3) * 7 + v] * xv;
        }
    }

    float* op = out + ((size_t)bz * HP + y0 + rbase) * WP + x0 + tx;
    op[0 * WP] = a0;
    op[1 * WP] = a1;
    op[2 * WP] = a2;
    op[3 * WP] = a3;
}

extern "C" void kernel_launch(void* const* d_in, const int* in_sizes, int n_in,
                              void* d_out, int out_size)
{
    const float* cube = (const float*)d_in[0];
    const float* psf  = (const float*)d_in[1];
    const float* dx   = (const float*)d_in[2];
    const float* dy   = (const float*)d_in[3];
    float* out = (float*)d_out;

    dim3 gb(6, 6, BATCH * NK), tb(32, 8);
    accum_kernel<<<gb, tb>>>(cube, dx, dy);

    dim3 gc(6, 6, BATCH * NK), tc(32, 8);
    conv_kernel<<<gc, tc>>>(psf, out);
}